// round 7
// baseline (speedup 1.0000x reference)
#include <cuda_runtime.h>
#include <math.h>
#include <stdint.h>

#define Bsz  4
#define Cdim 512
#define HCd  64
#define Npix 4096

// ---- scratch (static device allocations; no cudaMalloc allowed) ----
__device__ float g_scale[4];                 // 1/sigma for Wf, Wg, Wh, Wv
__device__ float g_f[Bsz * Npix * HCd];      // [B][N][HC]
__device__ float g_g[Bsz * Npix * HCd];
__device__ float g_h[Bsz * Npix * HCd];
__device__ float g_o[Bsz * Npix * HCd];

// ---- mma helper: tf32 m16n8k8 (raw fp32 bits in; HW truncates mantissa) ----
__device__ __forceinline__ void mma8(float* c, const uint32_t* a, const uint32_t* b) {
    asm volatile(
        "mma.sync.aligned.m16n8k8.row.col.f32.tf32.tf32.f32 "
        "{%0,%1,%2,%3}, {%4,%5,%6,%7}, {%8,%9}, {%0,%1,%2,%3};"
        : "+f"(c[0]), "+f"(c[1]), "+f"(c[2]), "+f"(c[3])
        : "r"(a[0]), "r"(a[1]), "r"(a[2]), "r"(a[3]), "r"(b[0]), "r"(b[1]));
}

__device__ __forceinline__ void cp16(void* sdst, const void* gsrc) {
    uint32_t s = (uint32_t)__cvta_generic_to_shared(sdst);
    asm volatile("cp.async.cg.shared.global [%0], [%1], 16;" :: "r"(s), "l"(gsrc));
}

// ============================================================================
// 1) sigma = ||W (W^T u)|| / ||W^T u||   ->  store 1/sigma
// ============================================================================
__global__ void sigma_kernel(const float* __restrict__ Wf, const float* __restrict__ uf,
                             const float* __restrict__ Wg, const float* __restrict__ ug,
                             const float* __restrict__ Wh, const float* __restrict__ uh,
                             const float* __restrict__ Wv, const float* __restrict__ uv) {
    __shared__ float su[512];
    __shared__ float sv[512];
    __shared__ float sred[512];
    __shared__ float s_nv2;

    int idx = blockIdx.x;
    const float* W; const float* u; int R, Cn;
    if (idx == 0)      { W = Wf; u = uf; R = 64;  Cn = 512; }
    else if (idx == 1) { W = Wg; u = ug; R = 64;  Cn = 512; }
    else if (idx == 2) { W = Wh; u = uh; R = 64;  Cn = 512; }
    else               { W = Wv; u = uv; R = 512; Cn = 64;  }

    int t = threadIdx.x;
    if (t < R) su[t] = u[t];
    __syncthreads();

    float nv2p = 0.f;
    for (int c = t; c < Cn; c += 512) {
        float acc = 0.f;
        for (int r = 0; r < R; r++) acc += W[r * Cn + c] * su[r];
        sv[c] = acc;
        nv2p += acc * acc;
    }
    sred[t] = nv2p;
    __syncthreads();
    for (int s = 256; s > 0; s >>= 1) { if (t < s) sred[t] += sred[t + s]; __syncthreads(); }
    if (t == 0) s_nv2 = sred[0];
    __syncthreads();

    float nw2p = 0.f;
    for (int r = t; r < R; r += 512) {
        float acc = 0.f;
        for (int c = 0; c < Cn; c++) acc += W[r * Cn + c] * sv[c];
        nw2p += acc * acc;
    }
    sred[t] = nw2p;
    __syncthreads();
    for (int s = 256; s > 0; s >>= 1) { if (t < s) sred[t] += sred[t + s]; __syncthreads(); }
    if (t == 0) g_scale[idx] = sqrtf(s_nv2 / sred[0]);   // 1/sigma
}

// ============================================================================
// 2) Fused projections f/g/h via tf32 mma.
//    CTA: 128 pixels x 192 outputs (f|g|h). K=512 in 32-chunks.
//    8 warps; warp handles 16 pixel rows x all 192 cols.
// ============================================================================
__global__ void __launch_bounds__(256) fgh_mma_kernel(
    const float* __restrict__ x,
    const float* __restrict__ Wf, const float* __restrict__ bf,
    const float* __restrict__ Wg, const float* __restrict__ bg,
    const float* __restrict__ Wh, const float* __restrict__ bh) {
    __shared__ float xs[128 * 36];   // [pix][c] transposed x tile
    __shared__ float ws[192 * 36];   // [outRow][c], scale folded

    int b = blockIdx.y;
    int n0 = blockIdx.x * 128;
    int tid = threadIdx.x;
    int warp = tid >> 5, lane = tid & 31;
    int gr = lane >> 2, tg = lane & 3;
    int qr = warp * 16;

    float sf = g_scale[0], sg = g_scale[1], sh = g_scale[2];

    float acc[24][4];
    #pragma unroll
    for (int nt = 0; nt < 24; nt++) acc[nt][0] = acc[nt][1] = acc[nt][2] = acc[nt][3] = 0.f;

    for (int c0 = 0; c0 < Cdim; c0 += 32) {
        __syncthreads();
        // x tile: 32 c x 128 pix -> xs[pix][c]
        #pragma unroll
        for (int i = 0; i < 16; i++) {
            int id = tid + i * 256;
            int cc = id >> 7, nn = id & 127;
            xs[nn * 36 + cc] = x[((size_t)b * Cdim + c0 + cc) * Npix + n0 + nn];
        }
        // weights: 192 rows x 32 c
        #pragma unroll
        for (int i = 0; i < 24; i++) {
            int id = tid + i * 256;
            int row = id >> 5, cc = id & 31;
            float w;
            if (row < 64)       w = Wf[row * Cdim + c0 + cc] * sf;
            else if (row < 128) w = Wg[(row - 64) * Cdim + c0 + cc] * sg;
            else                w = Wh[(row - 128) * Cdim + c0 + cc] * sh;
            ws[row * 36 + cc] = w;
        }
        __syncthreads();

        uint32_t a[4][4];
        #pragma unroll
        for (int kt = 0; kt < 4; kt++) {
            int c = kt * 8 + tg;
            a[kt][0] = __float_as_uint(xs[(qr + gr) * 36 + c]);
            a[kt][1] = __float_as_uint(xs[(qr + gr + 8) * 36 + c]);
            a[kt][2] = __float_as_uint(xs[(qr + gr) * 36 + c + 4]);
            a[kt][3] = __float_as_uint(xs[(qr + gr + 8) * 36 + c + 4]);
        }
        #pragma unroll
        for (int nt = 0; nt < 24; nt++) {
            #pragma unroll
            for (int kt = 0; kt < 4; kt++) {
                uint32_t bb[2];
                int rw = nt * 8 + gr, c = kt * 8 + tg;
                bb[0] = __float_as_uint(ws[rw * 36 + c]);
                bb[1] = __float_as_uint(ws[rw * 36 + c + 4]);
                mma8(acc[nt], a[kt], bb);
            }
        }
    }

    // epilogue: bias + store. Thread owns D[gr][nt*8+2tg(+1)], rows gr, gr+8.
    int row0 = n0 + qr + gr, row1 = row0 + 8;
    #pragma unroll
    for (int nt = 0; nt < 24; nt++) {
        int mat = nt >> 3;
        int lcol = (nt & 7) * 8 + 2 * tg;
        float* dst; const float* bias;
        if (mat == 0)      { dst = g_f; bias = bf; }
        else if (mat == 1) { dst = g_g; bias = bg; }
        else               { dst = g_h; bias = bh; }
        float b0 = bias[lcol], b1 = bias[lcol + 1];
        *(float2*)&dst[((size_t)b * Npix + row0) * HCd + lcol] =
            make_float2(acc[nt][0] + b0, acc[nt][1] + b1);
        *(float2*)&dst[((size_t)b * Npix + row1) * HCd + lcol] =
            make_float2(acc[nt][2] + b0, acc[nt][3] + b1);
    }
}

// ============================================================================
// 3) Flash attention, tf32 mma + cp.async 3-slot pipelined K/V (R3, verified)
// ============================================================================
#define QT 128
#define KT 64
#define NTILES (Npix / KT)

__global__ void __launch_bounds__(256, 1) attn_mma_kernel() {
    extern __shared__ float smem[];
    float* qs = smem;                   // [128][68]
    float* ksb = qs + QT * 68;          // 3 x [64][68]
    float* vsb = ksb + 3 * KT * 68;     // 3 x [64][72]
    float* ps = vsb + 3 * KT * 72;      // [128][68]

    int b = blockIdx.y;
    int q0g = blockIdx.x * QT;
    int tid = threadIdx.x;
    int warp = tid >> 5, lane = tid & 31;
    int gr = lane >> 2, tg = lane & 3;
    int qr = warp * 16;

    int prow[4], pc4[4];
    #pragma unroll
    for (int i = 0; i < 4; i++) {
        int id = tid + i * 256;
        prow[i] = id >> 4; pc4[i] = (id & 15) * 4;
    }
    const float* gK = g_g + (size_t)b * Npix * HCd;
    const float* gV = g_h + (size_t)b * Npix * HCd;

    #pragma unroll
    for (int st = 0; st < 2; st++) {
        float* kd = ksb + st * KT * 68;
        float* vd = vsb + st * KT * 72;
        #pragma unroll
        for (int i = 0; i < 4; i++) {
            size_t gb = (size_t)(st * KT + prow[i]) * HCd + pc4[i];
            cp16(&kd[prow[i] * 68 + pc4[i]], gK + gb);
            cp16(&vd[prow[i] * 72 + pc4[i]], gV + gb);
        }
        asm volatile("cp.async.commit_group;");
    }

    #pragma unroll
    for (int i = 0; i < 8; i++) {
        int id = tid + i * 256;
        int row = id >> 4, c4 = (id & 15) * 4;
        *(float4*)&qs[row * 68 + c4] =
            *(const float4*)&g_f[((size_t)b * Npix + q0g + row) * HCd + c4];
    }
    __syncthreads();

    uint32_t a[8][4];
    #pragma unroll
    for (int kt = 0; kt < 8; kt++) {
        int c = kt * 8 + tg;
        a[kt][0] = __float_as_uint(qs[(qr + gr) * 68 + c]);
        a[kt][1] = __float_as_uint(qs[(qr + gr + 8) * 68 + c]);
        a[kt][2] = __float_as_uint(qs[(qr + gr) * 68 + c + 4]);
        a[kt][3] = __float_as_uint(qs[(qr + gr + 8) * 68 + c + 4]);
    }

    float o[8][4];
    #pragma unroll
    for (int dt = 0; dt < 8; dt++) { o[dt][0] = o[dt][1] = o[dt][2] = o[dt][3] = 0.f; }
    float rmax0 = -1e30f, rmax1 = -1e30f, rsum0 = 0.f, rsum1 = 0.f;

    int slot = 0;
    for (int t = 0; t < NTILES; t++) {
        if (t == NTILES - 1) asm volatile("cp.async.wait_group 0;");
        else                 asm volatile("cp.async.wait_group 1;");
        __syncthreads();

        if (t + 2 < NTILES) {
            int st = (slot + 2) % 3;
            float* kd = ksb + st * KT * 68;
            float* vd = vsb + st * KT * 72;
            int m0 = (t + 2) * KT;
            #pragma unroll
            for (int i = 0; i < 4; i++) {
                size_t gb = (size_t)(m0 + prow[i]) * HCd + pc4[i];
                cp16(&kd[prow[i] * 68 + pc4[i]], gK + gb);
                cp16(&vd[prow[i] * 72 + pc4[i]], gV + gb);
            }
            asm volatile("cp.async.commit_group;");
        }

        const float* ks = ksb + slot * KT * 68;
        const float* vs = vsb + slot * KT * 72;

        float s[8][4];
        #pragma unroll
        for (int nt = 0; nt < 8; nt++) { s[nt][0] = s[nt][1] = s[nt][2] = s[nt][3] = 0.f; }
        #pragma unroll
        for (int kt = 0; kt < 8; kt++) {
            #pragma unroll
            for (int nt = 0; nt < 8; nt++) {
                uint32_t bb[2];
                int n = nt * 8 + gr, c = kt * 8 + tg;
                bb[0] = __float_as_uint(ks[n * 68 + c]);
                bb[1] = __float_as_uint(ks[n * 68 + c + 4]);
                mma8(s[nt], a[kt], bb);
            }
        }

        float tm0 = -1e30f, tm1 = -1e30f;
        #pragma unroll
        for (int nt = 0; nt < 8; nt++) {
            tm0 = fmaxf(tm0, fmaxf(s[nt][0], s[nt][1]));
            tm1 = fmaxf(tm1, fmaxf(s[nt][2], s[nt][3]));
        }
        tm0 = fmaxf(tm0, __shfl_xor_sync(0xffffffffu, tm0, 1));
        tm0 = fmaxf(tm0, __shfl_xor_sync(0xffffffffu, tm0, 2));
        tm1 = fmaxf(tm1, __shfl_xor_sync(0xffffffffu, tm1, 1));
        tm1 = fmaxf(tm1, __shfl_xor_sync(0xffffffffu, tm1, 2));
        float nm0 = fmaxf(rmax0, tm0), nm1 = fmaxf(rmax1, tm1);
        float corr0 = __expf(rmax0 - nm0), corr1 = __expf(rmax1 - nm1);
        float ts0 = 0.f, ts1 = 0.f;
        #pragma unroll
        for (int nt = 0; nt < 8; nt++) {
            s[nt][0] = __expf(s[nt][0] - nm0);
            s[nt][1] = __expf(s[nt][1] - nm0);
            s[nt][2] = __expf(s[nt][2] - nm1);
            s[nt][3] = __expf(s[nt][3] - nm1);
            ts0 += s[nt][0] + s[nt][1];
            ts1 += s[nt][2] + s[nt][3];
        }
        ts0 += __shfl_xor_sync(0xffffffffu, ts0, 1);
        ts0 += __shfl_xor_sync(0xffffffffu, ts0, 2);
        ts1 += __shfl_xor_sync(0xffffffffu, ts1, 1);
        ts1 += __shfl_xor_sync(0xffffffffu, ts1, 2);
        rsum0 = rsum0 * corr0 + ts0; rmax0 = nm0;
        rsum1 = rsum1 * corr1 + ts1; rmax1 = nm1;
        #pragma unroll
        for (int dt = 0; dt < 8; dt++) {
            o[dt][0] *= corr0; o[dt][1] *= corr0;
            o[dt][2] *= corr1; o[dt][3] *= corr1;
        }

        #pragma unroll
        for (int nt = 0; nt < 8; nt++) {
            *(float2*)&ps[(qr + gr) * 68 + nt * 8 + 2 * tg] = make_float2(s[nt][0], s[nt][1]);
            *(float2*)&ps[(qr + gr + 8) * 68 + nt * 8 + 2 * tg] = make_float2(s[nt][2], s[nt][3]);
        }
        __syncwarp();
        uint32_t pa[8][4];
        #pragma unroll
        for (int kt = 0; kt < 8; kt++) {
            int c = kt * 8 + tg;
            pa[kt][0] = __float_as_uint(ps[(qr + gr) * 68 + c]);
            pa[kt][1] = __float_as_uint(ps[(qr + gr + 8) * 68 + c]);
            pa[kt][2] = __float_as_uint(ps[(qr + gr) * 68 + c + 4]);
            pa[kt][3] = __float_as_uint(ps[(qr + gr + 8) * 68 + c + 4]);
        }

        #pragma unroll
        for (int kt = 0; kt < 8; kt++) {
            #pragma unroll
            for (int dt = 0; dt < 8; dt++) {
                uint32_t bb[2];
                bb[0] = __float_as_uint(vs[(kt * 8 + tg) * 72 + dt * 8 + gr]);
                bb[1] = __float_as_uint(vs[(kt * 8 + tg + 4) * 72 + dt * 8 + gr]);
                mma8(o[dt], pa[kt], bb);
            }
        }

        slot++; if (slot == 3) slot = 0;
    }

    float inv0 = 1.f / rsum0, inv1 = 1.f / rsum1;
    #pragma unroll
    for (int dt = 0; dt < 8; dt++) {
        size_t r0 = ((size_t)b * Npix + q0g + qr + gr) * HCd + dt * 8 + 2 * tg;
        *(float2*)&g_o[r0] = make_float2(o[dt][0] * inv0, o[dt][1] * inv0);
        size_t r1 = ((size_t)b * Npix + q0g + qr + gr + 8) * HCd + dt * 8 + 2 * tg;
        *(float2*)&g_o[r1] = make_float2(o[dt][2] * inv1, o[dt][3] * inv1);
    }
}

// ============================================================================
// 4) Output projection via tf32 mma, fused bias/gamma/residual.
//    CTA: 128 pixels x 128 channels, K=64 (single load).
// ============================================================================
__global__ void __launch_bounds__(256) outproj_mma_kernel(
    const float* __restrict__ x, const float* __restrict__ Wv,
    const float* __restrict__ bv, const float* __restrict__ gamma,
    float* __restrict__ out) {
    extern __shared__ float sm2[];
    float* os = sm2;            // [128 pix][68]
    float* ws = sm2 + 128 * 68; // [128 c][68]

    int b = blockIdx.z;
    int c0 = blockIdx.y * 128;
    int n0 = blockIdx.x * 128;
    int tid = threadIdx.x;
    int warp = tid >> 5, lane = tid & 31;
    int gr = lane >> 2, tg = lane & 3;
    int qr = warp * 16;
    float sv = g_scale[3];

    #pragma unroll
    for (int i = 0; i < 8; i++) {
        int id = tid + i * 256;
        int row = id >> 4, k4 = (id & 15) * 4;
        *(float4*)&os[row * 68 + k4] =
            *(const float4*)&g_o[((size_t)b * Npix + n0 + row) * HCd + k4];
        float4 w = *(const float4*)&Wv[(size_t)(c0 + row) * HCd + k4];
        ws[row * 68 + k4 + 0] = w.x * sv;
        ws[row * 68 + k4 + 1] = w.y * sv;
        ws[row * 68 + k4 + 2] = w.z * sv;
        ws[row * 68 + k4 + 3] = w.w * sv;
    }
    __syncthreads();

    uint32_t a[8][4];
    #pragma unroll
    for (int kt = 0; kt < 8; kt++) {
        int c = kt * 8 + tg;
        a[kt][0] = __float_as_uint(os[(qr + gr) * 68 + c]);
        a[kt][1] = __float_as_uint(os[(qr + gr + 8) * 68 + c]);
        a[kt][2] = __float_as_uint(os[(qr + gr) * 68 + c + 4]);
        a[kt][3] = __float_as_uint(os[(qr + gr + 8) * 68 + c + 4]);
    }

    float acc[16][4];
    #pragma unroll
    for (int nt = 0; nt < 16; nt++) acc[nt][0] = acc[nt][1] = acc[nt][2] = acc[nt][3] = 0.f;
    #pragma unroll
    for (int nt = 0; nt < 16; nt++) {
        #pragma unroll
        for (int kt = 0; kt < 8; kt++) {
            uint32_t bb[2];
            int rw = nt * 8 + gr, c = kt * 8 + tg;
            bb[0] = __float_as_uint(ws[rw * 68 + c]);
            bb[1] = __float_as_uint(ws[rw * 68 + c + 4]);
            mma8(acc[nt], a[kt], bb);
        }
    }

    float gm = gamma[0];
    int nr0 = n0 + qr + gr, nr1 = nr0 + 8;
    #pragma unroll
    for (int nt = 0; nt < 16; nt++) {
        int c = c0 + nt * 8 + 2 * tg;
        float b0 = bv[c], b1 = bv[c + 1];
        size_t i00 = ((size_t)b * Cdim + c) * Npix + nr0;
        size_t i10 = i00 + Npix;            // c+1, row nr0
        size_t i01 = i00 + 8;               // c, row nr1
        size_t i11 = i10 + 8;
        out[i00] = gm * (acc[nt][0] + b0) + x[i00];
        out[i10] = gm * (acc[nt][1] + b1) + x[i10];
        out[i01] = gm * (acc[nt][2] + b0) + x[i01];
        out[i11] = gm * (acc[nt][3] + b1) + x[i11];
    }
}

// ============================================================================
// launcher
// ============================================================================
extern "C" void kernel_launch(void* const* d_in, const int* in_sizes, int n_in,
                              void* d_out, int out_size) {
    (void)in_sizes; (void)n_in; (void)out_size;
    const float* x  = (const float*)d_in[0];
    const float* Wf = (const float*)d_in[1];
    const float* bf = (const float*)d_in[2];
    const float* Wg = (const float*)d_in[3];
    const float* bg = (const float*)d_in[4];
    const float* Wh = (const float*)d_in[5];
    const float* bh = (const float*)d_in[6];
    const float* Wv = (const float*)d_in[7];
    const float* bv = (const float*)d_in[8];
    const float* uf = (const float*)d_in[9];
    const float* ug = (const float*)d_in[10];
    const float* uh = (const float*)d_in[11];
    const float* uv = (const float*)d_in[12];
    const float* gamma = (const float*)d_in[13];
    float* out = (float*)d_out;

    static int attrs_set = 0;
    const int attn_smem =
        (QT * 68 + 3 * KT * 68 + 3 * KT * 72 + QT * 68) * (int)sizeof(float); // 177152
    const int oproj_smem = 2 * 128 * 68 * (int)sizeof(float);                  // 69632
    if (!attrs_set) {
        cudaFuncSetAttribute(attn_mma_kernel, cudaFuncAttributeMaxDynamicSharedMemorySize,
                             attn_smem);
        cudaFuncSetAttribute(outproj_mma_kernel, cudaFuncAttributeMaxDynamicSharedMemorySize,
                             oproj_smem);
        attrs_set = 1;
    }

    sigma_kernel<<<4, 512>>>(Wf, uf, Wg, ug, Wh, uh, Wv, uv);
    fgh_mma_kernel<<<dim3(Npix / 128, Bsz), 256>>>(x, Wf, bf, Wg, bg, Wh, bh);
    attn_mma_kernel<<<dim3(Npix / QT, Bsz), 256, attn_smem>>>();
    outproj_mma_kernel<<<dim3(Npix / 128, Cdim / 128, Bsz), 256, oproj_smem>>>(
        x, Wv, bv, gamma, out);
}

// round 9
// speedup vs baseline: 1.4357x; 1.4357x over previous
#include <cuda_runtime.h>
#include <math.h>
#include <stdint.h>

#define Bsz  4
#define Cdim 512
#define HCd  64
#define Npix 4096

// ---- scratch (static device allocations; no cudaMalloc allowed) ----
__device__ float g_scale[4];                 // 1/sigma for Wf, Wg, Wh, Wv
__device__ float g_f[Bsz * Npix * HCd];      // [B][N][HC]
__device__ float g_g[Bsz * Npix * HCd];
__device__ float g_h[Bsz * Npix * HCd];
__device__ float g_o[Bsz * Npix * HCd];

// ---- mma helper: tf32 m16n8k8 (raw fp32 bits in; HW truncates mantissa) ----
__device__ __forceinline__ void mma8(float* c, const uint32_t* a, const uint32_t* b) {
    asm volatile(
        "mma.sync.aligned.m16n8k8.row.col.f32.tf32.tf32.f32 "
        "{%0,%1,%2,%3}, {%4,%5,%6,%7}, {%8,%9}, {%0,%1,%2,%3};"
        : "+f"(c[0]), "+f"(c[1]), "+f"(c[2]), "+f"(c[3])
        : "r"(a[0]), "r"(a[1]), "r"(a[2]), "r"(a[3]), "r"(b[0]), "r"(b[1]));
}

__device__ __forceinline__ void cp16(void* sdst, const void* gsrc) {
    uint32_t s = (uint32_t)__cvta_generic_to_shared(sdst);
    asm volatile("cp.async.cg.shared.global [%0], [%1], 16;" :: "r"(s), "l"(gsrc));
}

// ============================================================================
// 1) sigma = ||W (W^T u)|| / ||W^T u||   ->  store 1/sigma
// ============================================================================
__global__ void sigma_kernel(const float* __restrict__ Wf, const float* __restrict__ uf,
                             const float* __restrict__ Wg, const float* __restrict__ ug,
                             const float* __restrict__ Wh, const float* __restrict__ uh,
                             const float* __restrict__ Wv, const float* __restrict__ uv) {
    __shared__ float su[512];
    __shared__ float sv[512];
    __shared__ float sred[512];
    __shared__ float s_nv2;

    int idx = blockIdx.x;
    const float* W; const float* u; int R, Cn;
    if (idx == 0)      { W = Wf; u = uf; R = 64;  Cn = 512; }
    else if (idx == 1) { W = Wg; u = ug; R = 64;  Cn = 512; }
    else if (idx == 2) { W = Wh; u = uh; R = 64;  Cn = 512; }
    else               { W = Wv; u = uv; R = 512; Cn = 64;  }

    int t = threadIdx.x;
    if (t < R) su[t] = u[t];
    __syncthreads();

    float nv2p = 0.f;
    for (int c = t; c < Cn; c += 512) {
        float acc = 0.f;
        for (int r = 0; r < R; r++) acc += W[r * Cn + c] * su[r];
        sv[c] = acc;
        nv2p += acc * acc;
    }
    sred[t] = nv2p;
    __syncthreads();
    for (int s = 256; s > 0; s >>= 1) { if (t < s) sred[t] += sred[t + s]; __syncthreads(); }
    if (t == 0) s_nv2 = sred[0];
    __syncthreads();

    float nw2p = 0.f;
    for (int r = t; r < R; r += 512) {
        float acc = 0.f;
        for (int c = 0; c < Cn; c++) acc += W[r * Cn + c] * sv[c];
        nw2p += acc * acc;
    }
    sred[t] = nw2p;
    __syncthreads();
    for (int s = 256; s > 0; s >>= 1) { if (t < s) sred[t] += sred[t + s]; __syncthreads(); }
    if (t == 0) g_scale[idx] = sqrtf(s_nv2 / sred[0]);   // 1/sigma
}

// ============================================================================
// 2) Projections via tf32 mma, ONE matrix per CTA (blockIdx.z = f/g/h).
//    CTA: 128 pixels x 64 outputs, K=512 in 32-chunks.
//    Warp tile: 16 pixels x 64 outputs -> acc[8][4] = 32 regs, no spill.
// ============================================================================
__global__ void __launch_bounds__(256) fgh_mma_kernel(
    const float* __restrict__ x,
    const float* __restrict__ Wf, const float* __restrict__ bf,
    const float* __restrict__ Wg, const float* __restrict__ bg,
    const float* __restrict__ Wh, const float* __restrict__ bh) {
    __shared__ float xs[128 * 36];   // [pix][c]
    __shared__ float ws[64 * 36];    // [outRow][c], scale folded

    int b = blockIdx.y;
    int n0 = blockIdx.x * 128;
    int mat = blockIdx.z;
    int tid = threadIdx.x;
    int warp = tid >> 5, lane = tid & 31;
    int gr = lane >> 2, tg = lane & 3;
    int qr = warp * 16;

    const float* W; const float* bias; float* dst; float sc;
    if (mat == 0)      { W = Wf; bias = bf; dst = g_f; sc = g_scale[0]; }
    else if (mat == 1) { W = Wg; bias = bg; dst = g_g; sc = g_scale[1]; }
    else               { W = Wh; bias = bh; dst = g_h; sc = g_scale[2]; }

    float acc[8][4];
    #pragma unroll
    for (int nt = 0; nt < 8; nt++) acc[nt][0] = acc[nt][1] = acc[nt][2] = acc[nt][3] = 0.f;

    for (int c0 = 0; c0 < Cdim; c0 += 32) {
        __syncthreads();
        // x tile: 32 c x 128 pix -> xs[pix][c]
        #pragma unroll
        for (int i = 0; i < 16; i++) {
            int id = tid + i * 256;
            int cc = id >> 7, nn = id & 127;
            xs[nn * 36 + cc] = x[((size_t)b * Cdim + c0 + cc) * Npix + n0 + nn];
        }
        // weights: 64 rows x 32 c
        #pragma unroll
        for (int i = 0; i < 8; i++) {
            int id = tid + i * 256;
            int row = id >> 5, cc = id & 31;
            ws[row * 36 + cc] = W[row * Cdim + c0 + cc] * sc;
        }
        __syncthreads();

        uint32_t a[4][4];
        #pragma unroll
        for (int kt = 0; kt < 4; kt++) {
            int c = kt * 8 + tg;
            a[kt][0] = __float_as_uint(xs[(qr + gr) * 36 + c]);
            a[kt][1] = __float_as_uint(xs[(qr + gr + 8) * 36 + c]);
            a[kt][2] = __float_as_uint(xs[(qr + gr) * 36 + c + 4]);
            a[kt][3] = __float_as_uint(xs[(qr + gr + 8) * 36 + c + 4]);
        }
        #pragma unroll
        for (int nt = 0; nt < 8; nt++) {
            #pragma unroll
            for (int kt = 0; kt < 4; kt++) {
                uint32_t bb[2];
                int rw = nt * 8 + gr, c = kt * 8 + tg;
                bb[0] = __float_as_uint(ws[rw * 36 + c]);
                bb[1] = __float_as_uint(ws[rw * 36 + c + 4]);
                mma8(acc[nt], a[kt], bb);
            }
        }
    }

    int row0 = n0 + qr + gr, row1 = row0 + 8;
    #pragma unroll
    for (int nt = 0; nt < 8; nt++) {
        int lcol = nt * 8 + 2 * tg;
        float b0 = bias[lcol], b1 = bias[lcol + 1];
        *(float2*)&dst[((size_t)b * Npix + row0) * HCd + lcol] =
            make_float2(acc[nt][0] + b0, acc[nt][1] + b1);
        *(float2*)&dst[((size_t)b * Npix + row1) * HCd + lcol] =
            make_float2(acc[nt][2] + b0, acc[nt][3] + b1);
    }
}

// ============================================================================
// 3) Flash attention, tf32 mma + cp.async 3-slot pipelined K/V (R3, verified)
// ============================================================================
#define QT 128
#define KT 64
#define NTILES (Npix / KT)

__global__ void __launch_bounds__(256, 1) attn_mma_kernel() {
    extern __shared__ float smem[];
    float* qs = smem;                   // [128][68]
    float* ksb = qs + QT * 68;          // 3 x [64][68]
    float* vsb = ksb + 3 * KT * 68;     // 3 x [64][72]
    float* ps = vsb + 3 * KT * 72;      // [128][68]

    int b = blockIdx.y;
    int q0g = blockIdx.x * QT;
    int tid = threadIdx.x;
    int warp = tid >> 5, lane = tid & 31;
    int gr = lane >> 2, tg = lane & 3;
    int qr = warp * 16;

    int prow[4], pc4[4];
    #pragma unroll
    for (int i = 0; i < 4; i++) {
        int id = tid + i * 256;
        prow[i] = id >> 4; pc4[i] = (id & 15) * 4;
    }
    const float* gK = g_g + (size_t)b * Npix * HCd;
    const float* gV = g_h + (size_t)b * Npix * HCd;

    #pragma unroll
    for (int st = 0; st < 2; st++) {
        float* kd = ksb + st * KT * 68;
        float* vd = vsb + st * KT * 72;
        #pragma unroll
        for (int i = 0; i < 4; i++) {
            size_t gb = (size_t)(st * KT + prow[i]) * HCd + pc4[i];
            cp16(&kd[prow[i] * 68 + pc4[i]], gK + gb);
            cp16(&vd[prow[i] * 72 + pc4[i]], gV + gb);
        }
        asm volatile("cp.async.commit_group;");
    }

    #pragma unroll
    for (int i = 0; i < 8; i++) {
        int id = tid + i * 256;
        int row = id >> 4, c4 = (id & 15) * 4;
        *(float4*)&qs[row * 68 + c4] =
            *(const float4*)&g_f[((size_t)b * Npix + q0g + row) * HCd + c4];
    }
    __syncthreads();

    uint32_t a[8][4];
    #pragma unroll
    for (int kt = 0; kt < 8; kt++) {
        int c = kt * 8 + tg;
        a[kt][0] = __float_as_uint(qs[(qr + gr) * 68 + c]);
        a[kt][1] = __float_as_uint(qs[(qr + gr + 8) * 68 + c]);
        a[kt][2] = __float_as_uint(qs[(qr + gr) * 68 + c + 4]);
        a[kt][3] = __float_as_uint(qs[(qr + gr + 8) * 68 + c + 4]);
    }

    float o[8][4];
    #pragma unroll
    for (int dt = 0; dt < 8; dt++) { o[dt][0] = o[dt][1] = o[dt][2] = o[dt][3] = 0.f; }
    float rmax0 = -1e30f, rmax1 = -1e30f, rsum0 = 0.f, rsum1 = 0.f;

    int slot = 0;
    for (int t = 0; t < NTILES; t++) {
        if (t == NTILES - 1) asm volatile("cp.async.wait_group 0;");
        else                 asm volatile("cp.async.wait_group 1;");
        __syncthreads();

        if (t + 2 < NTILES) {
            int st = (slot + 2) % 3;
            float* kd = ksb + st * KT * 68;
            float* vd = vsb + st * KT * 72;
            int m0 = (t + 2) * KT;
            #pragma unroll
            for (int i = 0; i < 4; i++) {
                size_t gb = (size_t)(m0 + prow[i]) * HCd + pc4[i];
                cp16(&kd[prow[i] * 68 + pc4[i]], gK + gb);
                cp16(&vd[prow[i] * 72 + pc4[i]], gV + gb);
            }
            asm volatile("cp.async.commit_group;");
        }

        const float* ks = ksb + slot * KT * 68;
        const float* vs = vsb + slot * KT * 72;

        float s[8][4];
        #pragma unroll
        for (int nt = 0; nt < 8; nt++) { s[nt][0] = s[nt][1] = s[nt][2] = s[nt][3] = 0.f; }
        #pragma unroll
        for (int kt = 0; kt < 8; kt++) {
            #pragma unroll
            for (int nt = 0; nt < 8; nt++) {
                uint32_t bb[2];
                int n = nt * 8 + gr, c = kt * 8 + tg;
                bb[0] = __float_as_uint(ks[n * 68 + c]);
                bb[1] = __float_as_uint(ks[n * 68 + c + 4]);
                mma8(s[nt], a[kt], bb);
            }
        }

        float tm0 = -1e30f, tm1 = -1e30f;
        #pragma unroll
        for (int nt = 0; nt < 8; nt++) {
            tm0 = fmaxf(tm0, fmaxf(s[nt][0], s[nt][1]));
            tm1 = fmaxf(tm1, fmaxf(s[nt][2], s[nt][3]));
        }
        tm0 = fmaxf(tm0, __shfl_xor_sync(0xffffffffu, tm0, 1));
        tm0 = fmaxf(tm0, __shfl_xor_sync(0xffffffffu, tm0, 2));
        tm1 = fmaxf(tm1, __shfl_xor_sync(0xffffffffu, tm1, 1));
        tm1 = fmaxf(tm1, __shfl_xor_sync(0xffffffffu, tm1, 2));
        float nm0 = fmaxf(rmax0, tm0), nm1 = fmaxf(rmax1, tm1);
        float corr0 = __expf(rmax0 - nm0), corr1 = __expf(rmax1 - nm1);
        float ts0 = 0.f, ts1 = 0.f;
        #pragma unroll
        for (int nt = 0; nt < 8; nt++) {
            s[nt][0] = __expf(s[nt][0] - nm0);
            s[nt][1] = __expf(s[nt][1] - nm0);
            s[nt][2] = __expf(s[nt][2] - nm1);
            s[nt][3] = __expf(s[nt][3] - nm1);
            ts0 += s[nt][0] + s[nt][1];
            ts1 += s[nt][2] + s[nt][3];
        }
        ts0 += __shfl_xor_sync(0xffffffffu, ts0, 1);
        ts0 += __shfl_xor_sync(0xffffffffu, ts0, 2);
        ts1 += __shfl_xor_sync(0xffffffffu, ts1, 1);
        ts1 += __shfl_xor_sync(0xffffffffu, ts1, 2);
        rsum0 = rsum0 * corr0 + ts0; rmax0 = nm0;
        rsum1 = rsum1 * corr1 + ts1; rmax1 = nm1;
        #pragma unroll
        for (int dt = 0; dt < 8; dt++) {
            o[dt][0] *= corr0; o[dt][1] *= corr0;
            o[dt][2] *= corr1; o[dt][3] *= corr1;
        }

        #pragma unroll
        for (int nt = 0; nt < 8; nt++) {
            *(float2*)&ps[(qr + gr) * 68 + nt * 8 + 2 * tg] = make_float2(s[nt][0], s[nt][1]);
            *(float2*)&ps[(qr + gr + 8) * 68 + nt * 8 + 2 * tg] = make_float2(s[nt][2], s[nt][3]);
        }
        __syncwarp();
        uint32_t pa[8][4];
        #pragma unroll
        for (int kt = 0; kt < 8; kt++) {
            int c = kt * 8 + tg;
            pa[kt][0] = __float_as_uint(ps[(qr + gr) * 68 + c]);
            pa[kt][1] = __float_as_uint(ps[(qr + gr + 8) * 68 + c]);
            pa[kt][2] = __float_as_uint(ps[(qr + gr) * 68 + c + 4]);
            pa[kt][3] = __float_as_uint(ps[(qr + gr + 8) * 68 + c + 4]);
        }

        #pragma unroll
        for (int kt = 0; kt < 8; kt++) {
            #pragma unroll
            for (int dt = 0; dt < 8; dt++) {
                uint32_t bb[2];
                bb[0] = __float_as_uint(vs[(kt * 8 + tg) * 72 + dt * 8 + gr]);
                bb[1] = __float_as_uint(vs[(kt * 8 + tg + 4) * 72 + dt * 8 + gr]);
                mma8(o[dt], pa[kt], bb);
            }
        }

        slot++; if (slot == 3) slot = 0;
    }

    float inv0 = 1.f / rsum0, inv1 = 1.f / rsum1;
    #pragma unroll
    for (int dt = 0; dt < 8; dt++) {
        size_t r0 = ((size_t)b * Npix + q0g + qr + gr) * HCd + dt * 8 + 2 * tg;
        *(float2*)&g_o[r0] = make_float2(o[dt][0] * inv0, o[dt][1] * inv0);
        size_t r1 = ((size_t)b * Npix + q0g + qr + gr + 8) * HCd + dt * 8 + 2 * tg;
        *(float2*)&g_o[r1] = make_float2(o[dt][2] * inv1, o[dt][3] * inv1);
    }
}

// ============================================================================
// 4) out = gamma * (Wv_sn @ o + bv) + x   (fp32, R3 verified)
// ============================================================================
__global__ void __launch_bounds__(256) outproj_kernel(
    const float* __restrict__ x, const float* __restrict__ Wv,
    const float* __restrict__ bv, const float* __restrict__ gamma,
    float* __restrict__ out) {
    __shared__ float ot[64 * 68];
    __shared__ float wvs[64 * 68];

    int b = blockIdx.z;
    int c0 = blockIdx.y * 64;
    int n0 = blockIdx.x * 64;
    int t = threadIdx.x;
    int tx = t & 15, ty = t >> 4;
    float sv = g_scale[3];

    #pragma unroll
    for (int i = 0; i < 16; i++) {
        int id = t + i * 256;
        int r = id >> 6, qq = id & 63;
        ot[qq * 68 + r] = g_o[((size_t)b * Npix + n0 + r) * HCd + qq];
        wvs[r * 68 + qq] = Wv[(size_t)(c0 + r) * HCd + qq] * sv;
    }
    __syncthreads();

    float acc[4][4] = {{0}};
    #pragma unroll 8
    for (int k = 0; k < 64; k++) {
        float4 ov = *(const float4*)&ot[k * 68 + tx * 4];
        #pragma unroll
        for (int ci = 0; ci < 4; ci++) {
            float w = wvs[(ty * 4 + ci) * 68 + k];
            acc[ci][0] += w * ov.x; acc[ci][1] += w * ov.y;
            acc[ci][2] += w * ov.z; acc[ci][3] += w * ov.w;
        }
    }

    float gm = gamma[0];
    #pragma unroll
    for (int ci = 0; ci < 4; ci++) {
        int c = c0 + ty * 4 + ci;
        float bias = bv[c];
        size_t gi = ((size_t)b * Cdim + c) * Npix + n0 + tx * 4;
        float4 xin = *(const float4*)&x[gi];
        float4 r;
        r.x = gm * (acc[ci][0] + bias) + xin.x;
        r.y = gm * (acc[ci][1] + bias) + xin.y;
        r.z = gm * (acc[ci][2] + bias) + xin.z;
        r.w = gm * (acc[ci][3] + bias) + xin.w;
        *(float4*)&out[gi] = r;
    }
}

// ============================================================================
// launcher
// ============================================================================
extern "C" void kernel_launch(void* const* d_in, const int* in_sizes, int n_in,
                              void* d_out, int out_size) {
    (void)in_sizes; (void)n_in; (void)out_size;
    const float* x  = (const float*)d_in[0];
    const float* Wf = (const float*)d_in[1];
    const float* bf = (const float*)d_in[2];
    const float* Wg = (const float*)d_in[3];
    const float* bg = (const float*)d_in[4];
    const float* Wh = (const float*)d_in[5];
    const float* bh = (const float*)d_in[6];
    const float* Wv = (const float*)d_in[7];
    const float* bv = (const float*)d_in[8];
    const float* uf = (const float*)d_in[9];
    const float* ug = (const float*)d_in[10];
    const float* uh = (const float*)d_in[11];
    const float* uv = (const float*)d_in[12];
    const float* gamma = (const float*)d_in[13];
    float* out = (float*)d_out;

    static int attrs_set = 0;
    const int attn_smem =
        (QT * 68 + 3 * KT * 68 + 3 * KT * 72 + QT * 68) * (int)sizeof(float); // 177152
    if (!attrs_set) {
        cudaFuncSetAttribute(attn_mma_kernel, cudaFuncAttributeMaxDynamicSharedMemorySize,
                             attn_smem);
        attrs_set = 1;
    }

    sigma_kernel<<<4, 512>>>(Wf, uf, Wg, ug, Wh, uh, Wv, uv);
    fgh_mma_kernel<<<dim3(Npix / 128, Bsz, 3), 256>>>(x, Wf, bf, Wg, bg, Wh, bh);
    attn_mma_kernel<<<dim3(Npix / QT, Bsz), 256, attn_smem>>>();
    outproj_kernel<<<dim3(Npix / 64, Cdim / 64, Bsz), 256>>>(x, Wv, bv, gamma, out);
}